// round 10
// baseline (speedup 1.0000x reference)
#include <cuda_runtime.h>
#include <math.h>

#define LLEAF 2048
#define NNODES 4095
#define MEM 150
#define IN_DIM 300
#define HIDD 50
#define NCLS 5
#define HSTR 152
#define NTHR 480
#define NWARPS 15

typedef unsigned long long ull;

// Scratch (device globals: no allocations allowed)
__device__ float g_C[2][NNODES][HSTR];
__device__ float g_H[2][NNODES][HSTR];
__device__ float g_s[2][NNODES];
__device__ float g_red4[4];
__device__ float g_part[2][32][HSTR];
__device__ unsigned g_gen;
__device__ unsigned g_cnt;
__device__ unsigned g_cnt2[4 * 32];     // 4 sub-counters, 128B apart

__device__ __forceinline__ float sigf(float x) { return 1.f / (1.f + expf(-x)); }

__device__ __forceinline__ ull pack2(float a, float b) {
    ull r; asm("mov.b64 %0, {%1,%2};" : "=l"(r) : "f"(a), "f"(b)); return r;
}
__device__ __forceinline__ void ffma2(ull& d, ull a, ull b) {
    asm("fma.rn.f32x2 %0, %1, %2, %0;" : "+l"(d) : "l"(a), "l"(b));
}
__device__ __forceinline__ ull add2(ull a, ull b) {
    ull r; asm("add.rn.f32x2 %0, %1, %2;" : "=l"(r) : "l"(a), "l"(b)); return r;
}
__device__ __forceinline__ float2 unpack2(ull v) {
    float2 f; asm("mov.b64 {%0,%1}, %2;" : "=f"(f.x), "=f"(f.y) : "l"(v)); return f;
}
__device__ __forceinline__ unsigned ld_acq(unsigned* p) {
    unsigned v; asm volatile("ld.acquire.gpu.u32 %0, [%1];" : "=r"(v) : "l"(p) : "memory"); return v;
}
__device__ __forceinline__ void st_rel(unsigned* p, unsigned v) {
    asm volatile("st.release.gpu.u32 [%0], %1;" :: "l"(p), "r"(v) : "memory");
}

// Two-level sense-reversing grid barrier (self-resetting, monotone generation).
__device__ __forceinline__ void gbar() {
    __syncthreads();
    if (threadIdx.x == 0) {
        unsigned gen = ld_acq(&g_gen);
        __threadfence();
        bool done = false;
        if (gridDim.x >= 4) {
            int s = blockIdx.x & 3;
            unsigned cnt_s = ((unsigned)gridDim.x + 3u - (unsigned)s) >> 2;
            if (atomicAdd(&g_cnt2[s * 32], 1u) == cnt_s - 1u) {
                g_cnt2[s * 32] = 0u;
                __threadfence();
                if (atomicAdd(&g_cnt, 1u) == 3u) {
                    g_cnt = 0u;
                    st_rel(&g_gen, gen + 1u);
                    done = true;
                }
            }
        } else {
            if (atomicAdd(&g_cnt, 1u) == gridDim.x - 1u) {
                g_cnt = 0u;
                st_rel(&g_gen, gen + 1u);
                done = true;
            }
        }
        if (!done) while (ld_acq(&g_gen) == gen) __nanosleep(64);
    }
    __syncthreads();
}

// Group barrier for the attsum phase (group = 160 threads, 5 warps).
__device__ __forceinline__ void gsync(int grp) {
    asm volatile("bar.sync %0, %1;" :: "r"(grp + 1), "r"(160) : "memory");
}

// ---------------------------------------------------------------------------
// Shared memory union
// ---------------------------------------------------------------------------
struct __align__(16) LvlS {
    float sl[MEM][16], sr[MEM][16];   // 16-float rows: aligned LDS.128 reads
    float2 buf[2][MEM][4];            // per-gate split-K buffer
    int li[8], ri[8], tt[8], kk[8];
};
struct __align__(16) LeafS {
    float xs[IN_DIM][16];
    float2 buf[2][MEM][8];
    int toks[16];
};
struct AttS { float w[3][128]; };
struct FinS {
    float q0[HSTR], q1[HSTR], beta[HSTR], alpha[HSTR];
    float slh[HSTR], srh[HSTR], hid[64], lg[8];
    float red[NWARPS + 1]; float bc;
};
union SmemU { LvlS lvl; LeafS leaf; AttS att; FinS fin; };

// ---------------------------------------------------------------------------
// Leaf task: 16 leaves, split-K=3 (k-slices of 100), KU=5 chunks.
// Fill loop is r-fastest: conflict-free STS with 16-float row stride.
// ---------------------------------------------------------------------------
__device__ void leaf_task(
    SmemU& smu, int task, int tid, int grp, int j,
    const int* __restrict__ ltok, const int* __restrict__ rtok,
    const float* __restrict__ emb, const float* __restrict__ Wx,
    const float* __restrict__ bx, const float* __restrict__ bh)
{
    LeafS& s = smu.leaf;
    const int t = task >> 7;
    const int g = task & 127;
    const int leaf0 = g * 16;
    const int* tok = t ? rtok : ltok;

    if (tid < 16) s.toks[tid] = tok[leaf0 + tid];
    __syncthreads();
    for (int idx = tid; idx < 16 * IN_DIM; idx += NTHR) {
        int k = idx >> 4, r = idx & 15;
        s.xs[k][r] = emb[s.toks[r] * IN_DIM + k];
    }
    __syncthreads();

    float2 fa[24];
    if (j < MEM) {
        ull acc[24];
#pragma unroll
        for (int a = 0; a < 24; a++) acc[a] = 0ull;
        const int kb = grp * 100;
        for (int c = 0; c < 20; c++) {
            float w[5][3];
#pragma unroll
            for (int q = 0; q < 5; q++) {
                int k = kb + c * 5 + q;
                w[q][0] = Wx[k * 450 + j];
                w[q][1] = Wx[k * 450 + 150 + j];
                w[q][2] = Wx[k * 450 + 300 + j];
            }
#pragma unroll
            for (int q = 0; q < 5; q++) {
                int k = kb + c * 5 + q;
                ull wi2 = pack2(w[q][0], w[q][0]);
                ull wo2 = pack2(w[q][1], w[q][1]);
                ull wu2 = pack2(w[q][2], w[q][2]);
                const ull* px = reinterpret_cast<const ull*>(&s.xs[k][0]);
#pragma unroll
                for (int p = 0; p < 8; p++) {
                    ull xv = px[p];
                    ffma2(acc[p], wi2, xv);
                    ffma2(acc[8 + p], wo2, xv);
                    ffma2(acc[16 + p], wu2, xv);
                }
            }
        }
#pragma unroll
        for (int a = 0; a < 24; a++) fa[a] = unpack2(acc[a]);
    }

#pragma unroll
    for (int gate = 0; gate < 3; gate++) {
        if (grp > 0 && j < MEM) {
#pragma unroll
            for (int p = 0; p < 8; p++) s.buf[grp - 1][j][p] = fa[gate * 8 + p];
        }
        __syncthreads();
        if (grp == 0 && j < MEM) {
#pragma unroll
            for (int sl = 0; sl < 2; sl++)
#pragma unroll
                for (int p = 0; p < 8; p++) {
                    float2 v = s.buf[sl][j][p];
                    fa[gate * 8 + p].x += v.x; fa[gate * 8 + p].y += v.y;
                }
        }
        __syncthreads();
    }

    if (grp == 0 && j < MEM) {
        float bi = bx[j] + bh[j];
        float bo = bx[150 + j] + bh[150 + j];
        float bu = bx[300 + j] + bh[300 + j];
#pragma unroll
        for (int p = 0; p < 8; p++) {
            float2 fi = fa[p], fo = fa[8 + p], fu = fa[16 + p];
#pragma unroll
            for (int h = 0; h < 2; h++) {
                float iv = sigf((h ? fi.y : fi.x) + bi);
                float ov = sigf((h ? fo.y : fo.x) + bo);
                float uv = tanhf((h ? fu.y : fu.x) + bu);
                float c2 = iv * uv;
                g_C[t][leaf0 + 2 * p + h][j] = c2;
                g_H[t][leaf0 + 2 * p + h][j] = ov * tanhf(c2);
            }
        }
    }
}

// ---------------------------------------------------------------------------
// Level task: R nodes (R in {2,4,8}), split-K=3, KU=5.
// hl+hr computed in-loop via add.f32x2 (no ss array); r-fastest fill.
// ---------------------------------------------------------------------------
template <int R>
__device__ void level_task(
    SmemU& smu, int task, int e0, int P, int tid, int grp, int j,
    const int* __restrict__ lidx, const int* __restrict__ ridx,
    const float* __restrict__ Wh, const float* __restrict__ bh,
    const float* __restrict__ Wf, const float* __restrict__ bf)
{
    LvlS& s = smu.lvl;
    constexpr int NP = R / 2;
    constexpr int LOGR = (R == 8) ? 3 : (R == 4) ? 2 : 1;
    if (tid < R) {
        int u = task * R + tid;
        int t = u / P;
        int e = e0 + (u - t * P);
        s.tt[tid] = t; s.kk[tid] = LLEAF + e;
        s.li[tid] = lidx[e]; s.ri[tid] = ridx[e];
    }
    __syncthreads();
    for (int idx = tid; idx < R * MEM; idx += NTHR) {
        int k = idx >> LOGR, r = idx & (R - 1);
        s.sl[k][r] = g_H[s.tt[r]][s.li[r]][k];
        s.sr[k][r] = g_H[s.tt[r]][s.ri[r]][k];
    }
    __syncthreads();

    float2 fa[5 * NP];
    float cl[R], cr[R];
    if (j < MEM) {
        if (grp == 0) {
#pragma unroll
            for (int r = 0; r < R; r++) {
                cl[r] = g_C[s.tt[r]][s.li[r]][j];
                cr[r] = g_C[s.tt[r]][s.ri[r]][j];
            }
        }
        ull acc[5 * NP];
#pragma unroll
        for (int a = 0; a < 5 * NP; a++) acc[a] = 0ull;
        const int kb = grp * 50;
        for (int c = 0; c < 10; c++) {
            float w[5][4];
#pragma unroll
            for (int q = 0; q < 5; q++) {
                int k = kb + c * 5 + q;
                w[q][0] = Wh[k * 450 + j];
                w[q][1] = Wh[k * 450 + 150 + j];
                w[q][2] = Wh[k * 450 + 300 + j];
                w[q][3] = Wf[k * 150 + j];
            }
#pragma unroll
            for (int q = 0; q < 5; q++) {
                int k = kb + c * 5 + q;
                ull wi2 = pack2(w[q][0], w[q][0]);
                ull wo2 = pack2(w[q][1], w[q][1]);
                ull wu2 = pack2(w[q][2], w[q][2]);
                ull wf2 = pack2(w[q][3], w[q][3]);
                const ull* pl = reinterpret_cast<const ull*>(&s.sl[k][0]);
                const ull* pr = reinterpret_cast<const ull*>(&s.sr[k][0]);
#pragma unroll
                for (int p = 0; p < NP; p++) {
                    ull lv = pl[p], rv = pr[p];
                    ull hs = add2(lv, rv);
                    ffma2(acc[0 * NP + p], wi2, hs);
                    ffma2(acc[1 * NP + p], wo2, hs);
                    ffma2(acc[2 * NP + p], wu2, hs);
                    ffma2(acc[3 * NP + p], wf2, lv);
                    ffma2(acc[4 * NP + p], wf2, rv);
                }
            }
        }
#pragma unroll
        for (int a = 0; a < 5 * NP; a++) fa[a] = unpack2(acc[a]);
    }

#pragma unroll
    for (int gate = 0; gate < 5; gate++) {
        if (grp > 0 && j < MEM) {
#pragma unroll
            for (int p = 0; p < NP; p++) s.buf[grp - 1][j][p] = fa[gate * NP + p];
        }
        __syncthreads();
        if (grp == 0 && j < MEM) {
#pragma unroll
            for (int sl = 0; sl < 2; sl++)
#pragma unroll
                for (int p = 0; p < NP; p++) {
                    float2 v = s.buf[sl][j][p];
                    fa[gate * NP + p].x += v.x; fa[gate * NP + p].y += v.y;
                }
        }
        __syncthreads();
    }

    if (grp == 0 && j < MEM) {
        float bi = bh[j], bo = bh[150 + j], bu = bh[300 + j], bfv = bf[j];
#pragma unroll
        for (int p = 0; p < NP; p++) {
            float2 fi = fa[p], fo = fa[NP + p], fu = fa[2 * NP + p];
            float2 ffl = fa[3 * NP + p], ffr = fa[4 * NP + p];
#pragma unroll
            for (int h = 0; h < 2; h++) {
                int r = 2 * p + h;
                float iv = sigf((h ? fi.y : fi.x) + bi);
                float ov = sigf((h ? fo.y : fo.x) + bo);
                float uv = tanhf((h ? fu.y : fu.x) + bu);
                float fl = sigf((h ? ffl.y : ffl.x) + bfv);
                float fr = sigf((h ? ffr.y : ffr.x) + bfv);
                int t = s.tt[r];
                float c2 = iv * uv + fl * cl[r] + fr * cr[r];
                g_C[t][s.kk[r]][j] = c2;
                g_H[t][s.kk[r]][j] = ov * tanhf(c2);
            }
        }
    }
    __syncthreads();
}

// ---------------------------------------------------------------------------
// One persistent kernel with grid barriers.
// ---------------------------------------------------------------------------
__global__ __launch_bounds__(NTHR, 1) void fused_kernel(
    const int* __restrict__ ltok, const int* __restrict__ rtok,
    const int* __restrict__ lidx, const int* __restrict__ ridx,
    const float* __restrict__ emb,
    const float* __restrict__ Wx, const float* __restrict__ bx,
    const float* __restrict__ Wh, const float* __restrict__ bh,
    const float* __restrict__ Wf, const float* __restrict__ bf,
    const float* __restrict__ Wa, const float* __restrict__ ba,
    const float* __restrict__ Wwh, const float* __restrict__ bwh,
    const float* __restrict__ Wwp, const float* __restrict__ bwp,
    float* __restrict__ out)
{
    __shared__ SmemU sm;
    const int tid = threadIdx.x;
    const int bid = blockIdx.x;
    const int grp = tid / 160;
    const int j = tid - grp * 160;

    // Leaf phase: 256 tasks x 16 leaves
    for (int task = bid; task < 256; task += gridDim.x)
        leaf_task(sm, task, tid, grp, j, ltok, rtok, emb, Wx, bx, bh);
    gbar();

    // Levels P=1024..4 with R=8
    {
        const int e0s[9] = {0, 1024, 1536, 1792, 1920, 1984, 2016, 2032, 2040};
        const int Ps[9]  = {1024, 512, 256, 128, 64, 32, 16, 8, 4};
        for (int lev = 0; lev < 9; lev++) {
            int P = Ps[lev], e0 = e0s[lev];
            int ntasks = 2 * P / 8;
            if (ntasks < 1) ntasks = 1;
            for (int task = bid; task < ntasks; task += gridDim.x)
                level_task<8>(sm, task, e0, P, tid, grp, j, lidx, ridx, Wh, bh, Wf, bf);
            gbar();
        }
    }
    // P=2: 4 nodes, one R=4 task
    if (bid == 0)
        level_task<4>(sm, 0, 2044, 2, tid, grp, j, lidx, ridx, Wh, bh, Wf, bf);
    gbar();
    // P=1: 2 nodes, one R=2 task
    if (bid == 0)
        level_task<2>(sm, 0, 2046, 1, tid, grp, j, lidx, ridx, Wh, bh, Wf, bf);
    gbar();

    // Attention scores (query vectors hoisted into registers)
    {
        int wid = tid >> 5, lane = tid & 31;
        float qa[5][2];
#pragma unroll
        for (int i = 0; i < 5; i++) {
            int k = lane + 32 * i;
            qa[i][0] = (k < MEM) ? g_H[0][NNODES - 1][k] : 0.f;
            qa[i][1] = (k < MEM) ? g_H[1][NNODES - 1][k] : 0.f;
        }
        for (int d = bid * NWARPS + wid; d < 2 * NNODES; d += gridDim.x * NWARPS) {
            int side = d / NNODES;
            int node = d - side * NNODES;
            int rt = 1 - side;
            float sum = 0.f;
#pragma unroll
            for (int i = 0; i < 5; i++) {
                int k = lane + 32 * i;
                if (k < MEM) sum += qa[i][side] * g_H[rt][node][k];
            }
#pragma unroll
            for (int off = 16; off; off >>= 1) sum += __shfl_xor_sync(0xffffffffu, sum, off);
            if (lane == 0) g_s[side][node] = sum;
        }
    }
    gbar();

    // Softmax normalizers (block 0)
    if (bid == 0) {
        const int lane = tid & 31, w = tid >> 5;
        for (int side = 0; side < 2; side++) {
            float m = -1e30f;
            for (int i = tid; i < NNODES; i += NTHR) m = fmaxf(m, g_s[side][i]);
#pragma unroll
            for (int off = 16; off; off >>= 1) m = fmaxf(m, __shfl_xor_sync(0xffffffffu, m, off));
            if (lane == 0) sm.fin.red[w] = m;
            __syncthreads();
            if (tid == 0) {
                float mm = sm.fin.red[0];
                for (int i = 1; i < NWARPS; i++) mm = fmaxf(mm, sm.fin.red[i]);
                sm.fin.bc = mm;
            }
            __syncthreads();
            float mx = sm.fin.bc;
            float s = 0.f;
            for (int i = tid; i < NNODES; i += NTHR) s += expf(g_s[side][i] - mx);
#pragma unroll
            for (int off = 16; off; off >>= 1) s += __shfl_xor_sync(0xffffffffu, s, off);
            __syncthreads();
            if (lane == 0) sm.fin.red[w] = s;
            __syncthreads();
            if (tid == 0) {
                float tot = 0.f;
                for (int i = 0; i < NWARPS; i++) tot += sm.fin.red[i];
                g_red4[side * 2] = mx;
                g_red4[side * 2 + 1] = 1.f / tot;
            }
            __syncthreads();
        }
    }
    gbar();

    // Attention weighted sums: 64 group tasks
    {
        int G = bid * 3 + grp, NG = gridDim.x * 3;
        for (int slot = G; slot < 64; slot += NG) {
            int side = slot >> 5, chunk = slot & 31, rt = 1 - side;
            int j0 = chunk * 128;
            float mx = g_red4[side * 2], inv = g_red4[side * 2 + 1];
            for (int jj = j; jj < 128; jj += 160) {
                int jg = j0 + jj;
                sm.att.w[grp][jj] = (jg < NNODES) ? expf(g_s[side][jg] - mx) * inv : 0.f;
            }
            gsync(grp);
            if (j < MEM) {
                float p = 0.f;
                int lim = min(128, NNODES - j0);
                for (int jj = 0; jj < lim; jj++)
                    p = fmaf(sm.att.w[grp][jj], g_H[rt][j0 + jj][j], p);
                g_part[side][chunk][j] = p;
            }
            gsync(grp);
        }
    }
    gbar();

    // Final head (block 0)
    if (bid == 0) {
        if (tid < MEM) {
            sm.fin.q0[tid] = g_H[0][NNODES - 1][tid];
            sm.fin.q1[tid] = g_H[1][NNODES - 1][tid];
            float b = 0.f, a = 0.f;
            for (int p = 0; p < 32; p++) { b += g_part[0][p][tid]; a += g_part[1][p][tid]; }
            sm.fin.beta[tid] = b; sm.fin.alpha[tid] = a;
        }
        __syncthreads();
        if (tid < MEM) {
            float lh = ba[tid], rh = ba[tid];
            for (int k = 0; k < MEM; k++) {
                float w1 = Wa[k * MEM + tid];
                float w2 = Wa[(MEM + k) * MEM + tid];
                lh += sm.fin.q0[k] * w1 + sm.fin.beta[k] * w2;
                rh += sm.fin.q1[k] * w1 + sm.fin.alpha[k] * w2;
            }
            sm.fin.slh[tid] = lh; sm.fin.srh[tid] = rh;
        }
        __syncthreads();
        if (tid < HIDD) {
            float acc = bwh[tid];
            for (int k = 0; k < MEM; k++) {
                float pr = sm.fin.slh[k] * sm.fin.srh[k];
                float ad = fabsf(sm.fin.slh[k] - sm.fin.srh[k]);
                acc += pr * Wwh[k * HIDD + tid] + ad * Wwh[(MEM + k) * HIDD + tid];
            }
            sm.fin.hid[tid] = 1.f / (1.f + expf(-acc));
        }
        __syncthreads();
        if (tid < NCLS) {
            float v = bwp[tid];
            for (int m = 0; m < HIDD; m++) v += sm.fin.hid[m] * Wwp[m * NCLS + tid];
            sm.fin.lg[tid] = v;
        }
        __syncthreads();
        if (tid < NCLS) {
            float mx = sm.fin.lg[0];
            for (int c = 1; c < NCLS; c++) mx = fmaxf(mx, sm.fin.lg[c]);
            float s = 0.f;
            for (int c = 0; c < NCLS; c++) s += expf(sm.fin.lg[c] - mx);
            out[tid] = sm.fin.lg[tid] - mx - logf(s);
        }
    }
}

// ---------------------------------------------------------------------------
extern "C" void kernel_launch(void* const* d_in, const int* in_sizes, int n_in,
                              void* d_out, int out_size)
{
    const int*   ltok = (const int*)d_in[0];
    const int*   rtok = (const int*)d_in[1];
    const int*   lidx = (const int*)d_in[2];
    const int*   ridx = (const int*)d_in[3];
    const float* emb  = (const float*)d_in[4];
    const float* Wx   = (const float*)d_in[5];
    const float* bx   = (const float*)d_in[6];
    const float* Wh   = (const float*)d_in[7];
    const float* bhh  = (const float*)d_in[8];
    // d_in[9] = W_fx, d_in[10] = b_fx : unused by the reference
    const float* Wf   = (const float*)d_in[11];
    const float* bf   = (const float*)d_in[12];
    const float* Wa   = (const float*)d_in[13];
    const float* ba   = (const float*)d_in[14];
    const float* Wwh  = (const float*)d_in[15];
    const float* bwh  = (const float*)d_in[16];
    const float* Wwp  = (const float*)d_in[17];
    const float* bwp  = (const float*)d_in[18];
    float* out = (float*)d_out;

    int dev = 0, nsm = 0;
    cudaGetDevice(&dev);
    cudaDeviceGetAttribute(&nsm, cudaDevAttrMultiProcessorCount, dev);
    if (nsm <= 0) nsm = 64;

    fused_kernel<<<nsm, NTHR>>>(ltok, rtok, lidx, ridx, emb, Wx, bx, Wh, bhh,
                                Wf, bf, Wa, ba, Wwh, bwh, Wwp, bwp, out);
}

// round 11
// speedup vs baseline: 1.2615x; 1.2615x over previous
#include <cuda_runtime.h>
#include <math.h>

#define LLEAF 2048
#define NNODES 4095
#define MEM 150
#define IN_DIM 300
#define HIDD 50
#define NCLS 5
#define HSTR 152
#define NTHR 480

typedef unsigned long long ull;

// Scratch (device globals: no allocations allowed)
__device__ float g_C[2][NNODES][HSTR];
__device__ float g_H[2][NNODES][HSTR];
__device__ float g_s[2][NNODES];
__device__ float g_red4[4];             // maxl, invsuml, maxr, invsumr
__device__ float g_part[2][32][HSTR];   // partial attention sums (deterministic)
__device__ unsigned g_gen;              // grid barrier generation
__device__ unsigned g_cnt;              // grid barrier top-level count
__device__ unsigned g_cnt2[4 * 32];     // 4 sub-counters, 128B apart

// Fast transcendentals: __expf/__fdividef (rel err ~2^-21, safe for 1e-3 tol).
__device__ __forceinline__ float sigf(float x) {
    return __fdividef(1.f, 1.f + __expf(-x));
}
__device__ __forceinline__ float ftanh(float x) {
    x = fminf(fmaxf(x, -15.f), 15.f);          // avoid inf/inf
    float e = __expf(2.f * x);
    return __fdividef(e - 1.f, e + 1.f);
}

__device__ __forceinline__ ull pack2(float a, float b) {
    ull r; asm("mov.b64 %0, {%1,%2};" : "=l"(r) : "f"(a), "f"(b)); return r;
}
__device__ __forceinline__ void ffma2(ull& d, ull a, ull b) {
    asm("fma.rn.f32x2 %0, %1, %2, %0;" : "+l"(d) : "l"(a), "l"(b));
}
__device__ __forceinline__ float2 unpack2(ull v) {
    float2 f; asm("mov.b64 {%0,%1}, %2;" : "=f"(f.x), "=f"(f.y) : "l"(v)); return f;
}

__device__ __forceinline__ unsigned ld_acq(unsigned* p) {
    unsigned v; asm volatile("ld.acquire.gpu.u32 %0, [%1];" : "=r"(v) : "l"(p) : "memory"); return v;
}
__device__ __forceinline__ void st_rel(unsigned* p, unsigned v) {
    asm volatile("st.release.gpu.u32 [%0], %1;" :: "l"(p), "r"(v) : "memory");
}

// Two-level sense-reversing grid barrier (self-resetting, monotone generation).
__device__ __forceinline__ void gbar() {
    __syncthreads();
    if (threadIdx.x == 0) {
        unsigned gen = ld_acq(&g_gen);
        __threadfence();
        bool done = false;
        if (gridDim.x >= 4) {
            int s = blockIdx.x & 3;
            unsigned cnt_s = ((unsigned)gridDim.x + 3u - (unsigned)s) >> 2;
            if (atomicAdd(&g_cnt2[s * 32], 1u) == cnt_s - 1u) {
                g_cnt2[s * 32] = 0u;
                __threadfence();
                if (atomicAdd(&g_cnt, 1u) == 3u) {
                    g_cnt = 0u;
                    st_rel(&g_gen, gen + 1u);
                    done = true;
                }
            }
        } else {
            if (atomicAdd(&g_cnt, 1u) == gridDim.x - 1u) {
                g_cnt = 0u;
                st_rel(&g_gen, gen + 1u);
                done = true;
            }
        }
        if (!done) while (ld_acq(&g_gen) == gen) __nanosleep(64);
    }
    __syncthreads();
}

// ---------------------------------------------------------------------------
// Shared-memory union across phases (identical to the 228us champion)
// ---------------------------------------------------------------------------
struct LvlS {                            // level phase (R <= 8)
    float ss[MEM][10], sl[MEM][10], sr[MEM][10];
    float2 buf[2][MEM][4];               // per-gate split-K wave buffer
    int li[8], ri[8], tt[8], kk[8];
};
struct LeafS {                           // leaf phase (16 leaves)
    float xs[IN_DIM][18];
    float2 buf[2][MEM][8];
    int toks[16];
};
struct AttS { float w[3][128]; };        // attsum phase (one chunk per group)
struct FinS {                            // reduce + final phases
    float q0[HSTR], q1[HSTR], beta[HSTR], alpha[HSTR];
    float slh[HSTR], srh[HSTR], hid[64], lg[8];
    float red[16]; float bc;
};
union SmemU { LvlS lvl; LeafS leaf; AttS att; FinS fin; };

// ---------------------------------------------------------------------------
// One level task: R nodes (R in {2,4,8}), split-K=3, f32x2 FMA, wave reduce.
// ---------------------------------------------------------------------------
template <int R>
__device__ __forceinline__ void level_task(
    SmemU& sm, int task, int e0, int P,
    const int* __restrict__ lidx, const int* __restrict__ ridx,
    const float* __restrict__ Wh, const float* __restrict__ bh,
    const float* __restrict__ Wf, const float* __restrict__ bf,
    int tid, int grp, int j)
{
    constexpr int NP = R / 2;
    if (tid < R) {
        int u = task * R + tid;
        int t = u / P;
        int e = e0 + (u - t * P);
        sm.lvl.tt[tid] = t;
        sm.lvl.kk[tid] = LLEAF + e;
        sm.lvl.li[tid] = lidx[e];
        sm.lvl.ri[tid] = ridx[e];
    }
    __syncthreads();
    for (int idx = tid; idx < R * MEM; idx += NTHR) {
        int r = idx / MEM, k = idx - r * MEM;
        float a = g_H[sm.lvl.tt[r]][sm.lvl.li[r]][k];
        float b = g_H[sm.lvl.tt[r]][sm.lvl.ri[r]][k];
        sm.lvl.sl[k][r] = a; sm.lvl.sr[k][r] = b; sm.lvl.ss[k][r] = a + b;
    }
    __syncthreads();

    ull acc[5 * NP];
#pragma unroll
    for (int a = 0; a < 5 * NP; a++) acc[a] = 0ull;

    if (j < MEM) {
        const int kb = grp * 50;
        for (int kc = 0; kc < 50; kc += 5) {
            float w[5][4];
#pragma unroll
            for (int q = 0; q < 5; q++) {
                int k = kb + kc + q;
                w[q][0] = Wh[k * 450 + j];
                w[q][1] = Wh[k * 450 + 150 + j];
                w[q][2] = Wh[k * 450 + 300 + j];
                w[q][3] = Wf[k * 150 + j];
            }
#pragma unroll
            for (int q = 0; q < 5; q++) {
                int k = kb + kc + q;
                ull wi2 = pack2(w[q][0], w[q][0]);
                ull wo2 = pack2(w[q][1], w[q][1]);
                ull wu2 = pack2(w[q][2], w[q][2]);
                ull wf2 = pack2(w[q][3], w[q][3]);
                const ull* ps = reinterpret_cast<const ull*>(&sm.lvl.ss[k][0]);
                const ull* pl = reinterpret_cast<const ull*>(&sm.lvl.sl[k][0]);
                const ull* pr = reinterpret_cast<const ull*>(&sm.lvl.sr[k][0]);
#pragma unroll
                for (int p = 0; p < NP; p++) {
                    ull hs = ps[p];
                    ffma2(acc[0 * NP + p], wi2, hs);
                    ffma2(acc[1 * NP + p], wo2, hs);
                    ffma2(acc[2 * NP + p], wu2, hs);
                    ffma2(acc[3 * NP + p], wf2, pl[p]);
                    ffma2(acc[4 * NP + p], wf2, pr[p]);
                }
            }
        }
    }

    float2 fa[5 * NP];
#pragma unroll
    for (int a = 0; a < 5 * NP; a++) fa[a] = unpack2(acc[a]);

#pragma unroll
    for (int gate = 0; gate < 5; gate++) {
        if (grp > 0 && j < MEM) {
#pragma unroll
            for (int p = 0; p < NP; p++) sm.lvl.buf[grp - 1][j][p] = fa[gate * NP + p];
        }
        __syncthreads();
        if (grp == 0 && j < MEM) {
#pragma unroll
            for (int s = 0; s < 2; s++)
#pragma unroll
                for (int p = 0; p < NP; p++) {
                    float2 v = sm.lvl.buf[s][j][p];
                    fa[gate * NP + p].x += v.x; fa[gate * NP + p].y += v.y;
                }
        }
        __syncthreads();
    }

    if (grp == 0 && j < MEM) {
        float bi = bh[j], bo = bh[150 + j], bu = bh[300 + j], bfv = bf[j];
#pragma unroll
        for (int p = 0; p < NP; p++) {
            float2 fi = fa[0 * NP + p], fo = fa[1 * NP + p], fu = fa[2 * NP + p];
            float2 ffl = fa[3 * NP + p], ffr = fa[4 * NP + p];
#pragma unroll
            for (int h = 0; h < 2; h++) {
                int r = 2 * p + h;
                float iv = sigf((h ? fi.y : fi.x) + bi);
                float ov = sigf((h ? fo.y : fo.x) + bo);
                float uv = ftanh((h ? fu.y : fu.x) + bu);
                float fl = sigf((h ? ffl.y : ffl.x) + bfv);
                float fr = sigf((h ? ffr.y : ffr.x) + bfv);
                int t = sm.lvl.tt[r];
                float c = iv * uv + fl * g_C[t][sm.lvl.li[r]][j] + fr * g_C[t][sm.lvl.ri[r]][j];
                g_C[t][sm.lvl.kk[r]][j] = c;
                g_H[t][sm.lvl.kk[r]][j] = ov * ftanh(c);
            }
        }
    }
    __syncthreads();
}

// ---------------------------------------------------------------------------
// The whole model as one persistent kernel with grid barriers.
// ---------------------------------------------------------------------------
__global__ __launch_bounds__(NTHR, 1) void fused_kernel(
    const int* __restrict__ ltok, const int* __restrict__ rtok,
    const int* __restrict__ lidx, const int* __restrict__ ridx,
    const float* __restrict__ emb,
    const float* __restrict__ Wx, const float* __restrict__ bx,
    const float* __restrict__ Wh, const float* __restrict__ bh,
    const float* __restrict__ Wf, const float* __restrict__ bf,
    const float* __restrict__ Wa, const float* __restrict__ ba,
    const float* __restrict__ Wwh, const float* __restrict__ bwh,
    const float* __restrict__ Wwp, const float* __restrict__ bwp,
    float* __restrict__ out)
{
    __shared__ SmemU sm;
    const int tid = threadIdx.x;
    const int bid = blockIdx.x;
    const int grp = tid / 160;
    const int j = tid - grp * 160;

    // ================= leaf phase: 256 tasks x 16 leaves ===================
    for (int task = bid; task < 256; task += gridDim.x) {
        int t = task >> 7;
        int g = task & 127;
        int leaf0 = g * 16;
        const int* tok = t ? rtok : ltok;
        if (tid < 16) sm.leaf.toks[tid] = tok[leaf0 + tid];
        __syncthreads();
        for (int idx = tid; idx < 16 * IN_DIM; idx += NTHR) {
            int r = idx / IN_DIM, k = idx - r * IN_DIM;
            sm.leaf.xs[k][r] = emb[sm.leaf.toks[r] * IN_DIM + k];
        }
        __syncthreads();

        ull acc[24];
#pragma unroll
        for (int a = 0; a < 24; a++) acc[a] = 0ull;
        if (j < MEM) {
            const int kb = grp * 100;
            for (int kc = 0; kc < 100; kc += 5) {
                float w[5][3];
#pragma unroll
                for (int q = 0; q < 5; q++) {
                    int k = kb + kc + q;
                    w[q][0] = Wx[k * 450 + j];
                    w[q][1] = Wx[k * 450 + 150 + j];
                    w[q][2] = Wx[k * 450 + 300 + j];
                }
#pragma unroll
                for (int q = 0; q < 5; q++) {
                    int k = kb + kc + q;
                    ull wi2 = pack2(w[q][0], w[q][0]);
                    ull wo2 = pack2(w[q][1], w[q][1]);
                    ull wu2 = pack2(w[q][2], w[q][2]);
                    const ull* px = reinterpret_cast<const ull*>(&sm.leaf.xs[k][0]);
#pragma unroll
                    for (int p = 0; p < 8; p++) {
                        ull xv = px[p];
                        ffma2(acc[p], wi2, xv);
                        ffma2(acc[8 + p], wo2, xv);
                        ffma2(acc[16 + p], wu2, xv);
                    }
                }
            }
        }
        float2 fa[24];
#pragma unroll
        for (int a = 0; a < 24; a++) fa[a] = unpack2(acc[a]);
#pragma unroll
        for (int gate = 0; gate < 3; gate++) {
            if (grp > 0 && j < MEM) {
#pragma unroll
                for (int p = 0; p < 8; p++) sm.leaf.buf[grp - 1][j][p] = fa[gate * 8 + p];
            }
            __syncthreads();
            if (grp == 0 && j < MEM) {
#pragma unroll
                for (int s = 0; s < 2; s++)
#pragma unroll
                    for (int p = 0; p < 8; p++) {
                        float2 v = sm.leaf.buf[s][j][p];
                        fa[gate * 8 + p].x += v.x; fa[gate * 8 + p].y += v.y;
                    }
            }
            __syncthreads();
        }
        if (grp == 0 && j < MEM) {
            float bi = bx[j] + bh[j];
            float bo = bx[150 + j] + bh[150 + j];
            float bu = bx[300 + j] + bh[300 + j];
#pragma unroll
            for (int p = 0; p < 8; p++) {
                float2 fi = fa[p], fo = fa[8 + p], fu = fa[16 + p];
#pragma unroll
                for (int h = 0; h < 2; h++) {
                    float iv = sigf((h ? fi.y : fi.x) + bi);
                    float ov = sigf((h ? fo.y : fo.x) + bo);
                    float uv = ftanh((h ? fu.y : fu.x) + bu);
                    float c = iv * uv;
                    g_C[t][leaf0 + 2 * p + h][j] = c;
                    g_H[t][leaf0 + 2 * p + h][j] = ov * ftanh(c);
                }
            }
        }
        __syncthreads();
    }
    gbar();

    // ================= 11 tree levels ======================================
    {
        const int e0s[11] = {0, 1024, 1536, 1792, 1920, 1984, 2016, 2032, 2040, 2044, 2046};
        const int Ps[11]  = {1024, 512, 256, 128, 64, 32, 16, 8, 4, 2, 1};
        for (int lev = 0; lev < 11; lev++) {
            int P = Ps[lev], e0 = e0s[lev];
            if (lev < 3) {
                int ntasks = 2 * P / 8;
                for (int task = bid; task < ntasks; task += gridDim.x)
                    level_task<8>(sm, task, e0, P, lidx, ridx, Wh, bh, Wf, bf, tid, grp, j);
            } else if (lev == 3) {
                int ntasks = 2 * P / 4;
                for (int task = bid; task < ntasks; task += gridDim.x)
                    level_task<4>(sm, task, e0, P, lidx, ridx, Wh, bh, Wf, bf, tid, grp, j);
            } else {
                int ntasks = 2 * P / 2;
                for (int task = bid; task < ntasks; task += gridDim.x)
                    level_task<2>(sm, task, e0, P, lidx, ridx, Wh, bh, Wf, bf, tid, grp, j);
            }
            gbar();
        }
    }

    // ================= attention scores ====================================
    {
        int wid = tid >> 5, lane = tid & 31;
        for (int d = bid * 15 + wid; d < 2 * NNODES; d += gridDim.x * 15) {
            int side = d / NNODES;
            int node = d - side * NNODES;
            int qt = side, rt = 1 - side;
            float sum = 0.f;
            for (int k = lane; k < MEM; k += 32)
                sum += g_H[qt][NNODES - 1][k] * g_H[rt][node][k];
#pragma unroll
            for (int off = 16; off; off >>= 1) sum += __shfl_xor_sync(0xffffffffu, sum, off);
            if (lane == 0) g_s[side][node] = sum;
        }
    }
    gbar();

    // ================= softmax normalizers (block 0) =======================
    if (bid == 0) {
        const int lane = tid & 31, w = tid >> 5;
        for (int side = 0; side < 2; side++) {
            float m = -1e30f;
            for (int i = tid; i < NNODES; i += NTHR) m = fmaxf(m, g_s[side][i]);
#pragma unroll
            for (int off = 16; off; off >>= 1) m = fmaxf(m, __shfl_xor_sync(0xffffffffu, m, off));
            if (lane == 0) sm.fin.red[w] = m;
            __syncthreads();
            if (tid == 0) {
                float mm = sm.fin.red[0];
                for (int i = 1; i < 15; i++) mm = fmaxf(mm, sm.fin.red[i]);
                sm.fin.bc = mm;
            }
            __syncthreads();
            float mx = sm.fin.bc;
            float s = 0.f;
            for (int i = tid; i < NNODES; i += NTHR) s += __expf(g_s[side][i] - mx);
#pragma unroll
            for (int off = 16; off; off >>= 1) s += __shfl_xor_sync(0xffffffffu, s, off);
            __syncthreads();
            if (lane == 0) sm.fin.red[w] = s;
            __syncthreads();
            if (tid == 0) {
                float tot = 0.f;
                for (int i = 0; i < 15; i++) tot += sm.fin.red[i];
                g_red4[side * 2] = mx;
                g_red4[side * 2 + 1] = __fdividef(1.f, tot);
            }
            __syncthreads();
        }
    }
    gbar();

    // ================= attention weighted sums =============================
    {
        int slot = bid * 3 + grp;              // 64 tasks: (side, chunk)
        bool active = slot < 64;
        int side = slot >> 5, chunk = slot & 31, rt = 1 - side;
        int j0 = chunk * 128;
        if (active) {
            float mx = g_red4[side * 2], inv = g_red4[side * 2 + 1];
            for (int jj = j; jj < 128; jj += 160) {
                int jg = j0 + jj;
                sm.att.w[grp][jj] = (jg < NNODES) ? __expf(g_s[side][jg] - mx) * inv : 0.f;
            }
        }
        __syncthreads();
        if (active && j < MEM) {
            float p = 0.f;
            int lim = min(128, NNODES - j0);
            for (int jj = 0; jj < lim; jj++)
                p = fmaf(sm.att.w[grp][jj], g_H[rt][j0 + jj][j], p);
            g_part[side][chunk][j] = p;
        }
    }
    gbar();

    // ================= final head (block 0) ================================
    if (bid == 0) {
        if (tid < MEM) {
            sm.fin.q0[tid] = g_H[0][NNODES - 1][tid];
            sm.fin.q1[tid] = g_H[1][NNODES - 1][tid];
            float b = 0.f, a = 0.f;
            for (int p = 0; p < 32; p++) { b += g_part[0][p][tid]; a += g_part[1][p][tid]; }
            sm.fin.beta[tid] = b; sm.fin.alpha[tid] = a;
        }
        __syncthreads();
        if (tid < MEM) {
            float lh = ba[tid], rh = ba[tid];
            for (int k = 0; k < MEM; k++) {
                float w1 = Wa[k * MEM + tid];
                float w2 = Wa[(MEM + k) * MEM + tid];
                lh += sm.fin.q0[k] * w1 + sm.fin.beta[k] * w2;
                rh += sm.fin.q1[k] * w1 + sm.fin.alpha[k] * w2;
            }
            sm.fin.slh[tid] = lh; sm.fin.srh[tid] = rh;
        }
        __syncthreads();
        if (tid < HIDD) {
            float acc = bwh[tid];
            for (int k = 0; k < MEM; k++) {
                float pr = sm.fin.slh[k] * sm.fin.srh[k];
                float ad = fabsf(sm.fin.slh[k] - sm.fin.srh[k]);
                acc += pr * Wwh[k * HIDD + tid] + ad * Wwh[(MEM + k) * HIDD + tid];
            }
            sm.fin.hid[tid] = sigf(acc);
        }
        __syncthreads();
        if (tid < NCLS) {
            float v = bwp[tid];
            for (int m = 0; m < HIDD; m++) v += sm.fin.hid[m] * Wwp[m * NCLS + tid];
            sm.fin.lg[tid] = v;
        }
        __syncthreads();
        if (tid < NCLS) {
            float mx = sm.fin.lg[0];
            for (int c = 1; c < NCLS; c++) mx = fmaxf(mx, sm.fin.lg[c]);
            float s = 0.f;
            for (int c = 0; c < NCLS; c++) s += __expf(sm.fin.lg[c] - mx);
            out[tid] = sm.fin.lg[tid] - mx - __logf(s);
        }
    }
}

// ---------------------------------------------------------------------------
extern "C" void kernel_launch(void* const* d_in, const int* in_sizes, int n_in,
                              void* d_out, int out_size)
{
    const int*   ltok = (const int*)d_in[0];
    const int*   rtok = (const int*)d_in[1];
    const int*   lidx = (const int*)d_in[2];
    const int*   ridx = (const int*)d_in[3];
    const float* emb  = (const float*)d_in[4];
    const float* Wx   = (const float*)d_in[5];
    const float* bx   = (const float*)d_in[6];
    const float* Wh   = (const float*)d_in[7];
    const float* bhh  = (const float*)d_in[8];
    // d_in[9] = W_fx, d_in[10] = b_fx : unused by the reference
    const float* Wf   = (const float*)d_in[11];
    const float* bf   = (const float*)d_in[12];
    const float* Wa   = (const float*)d_in[13];
    const float* ba   = (const float*)d_in[14];
    const float* Wwh  = (const float*)d_in[15];
    const float* bwh  = (const float*)d_in[16];
    const float* Wwp  = (const float*)d_in[17];
    const float* bwp  = (const float*)d_in[18];
    float* out = (float*)d_out;

    int dev = 0, nsm = 0;
    cudaGetDevice(&dev);
    cudaDeviceGetAttribute(&nsm, cudaDevAttrMultiProcessorCount, dev);
    if (nsm <= 0) nsm = 64;   // conservative fallback, still correct

    fused_kernel<<<nsm, NTHR>>>(ltok, rtok, lidx, ridx, emb, Wx, bx, Wh, bhh,
                                Wf, bf, Wa, ba, Wwh, bwh, Wwp, bwp, out);
}